// round 1
// baseline (speedup 1.0000x reference)
#include <cuda_runtime.h>
#include <cuda_bf16.h>

// Weighted BCE mean reduction.
// loss_i = y_i==1 ? -log(x_i)*w1 : -log(1-x_i)*w0 ; out = mean(loss)
// N = 33554432 (divisible by 4), HBM-bound: 256 MB read -> ~32 us floor.

#define RBLOCKS 1184          // 148 SMs * 8
#define RTHREADS 256

__device__ float g_partials[RBLOCKS];

__global__ __launch_bounds__(RTHREADS, 8)
void wbce_reduce_kernel(const float4* __restrict__ x4,
                        const int4* __restrict__ y4,
                        const float* __restrict__ w,
                        int n4)
{
    const float w0 = __ldg(&w[0]);
    const float w1 = __ldg(&w[1]);

    float acc = 0.0f;
    const int stride = gridDim.x * blockDim.x;
    for (int i = blockIdx.x * blockDim.x + threadIdx.x; i < n4; i += stride) {
        float4 xv = x4[i];
        int4   yv = y4[i];
        // select operand + weight FIRST -> one MUFU log per element
        float t0 = (yv.x == 1) ? xv.x : (1.0f - xv.x);
        float t1 = (yv.y == 1) ? xv.y : (1.0f - xv.y);
        float t2 = (yv.z == 1) ? xv.z : (1.0f - xv.z);
        float t3 = (yv.w == 1) ? xv.w : (1.0f - xv.w);
        float u0 = (yv.x == 1) ? w1 : w0;
        float u1 = (yv.y == 1) ? w1 : w0;
        float u2 = (yv.z == 1) ? w1 : w0;
        float u3 = (yv.w == 1) ? w1 : w0;
        acc = fmaf(-__logf(t0), u0, acc);
        acc = fmaf(-__logf(t1), u1, acc);
        acc = fmaf(-__logf(t2), u2, acc);
        acc = fmaf(-__logf(t3), u3, acc);
    }

    // warp reduce
    #pragma unroll
    for (int off = 16; off > 0; off >>= 1)
        acc += __shfl_xor_sync(0xFFFFFFFFu, acc, off);

    __shared__ float warp_sums[RTHREADS / 32];
    int lane = threadIdx.x & 31;
    int wid  = threadIdx.x >> 5;
    if (lane == 0) warp_sums[wid] = acc;
    __syncthreads();

    if (wid == 0) {
        float v = (lane < RTHREADS / 32) ? warp_sums[lane] : 0.0f;
        #pragma unroll
        for (int off = 16; off > 0; off >>= 1)
            v += __shfl_xor_sync(0xFFFFFFFFu, v, off);
        if (lane == 0) g_partials[blockIdx.x] = v;
    }
}

__global__ __launch_bounds__(1024, 1)
void wbce_finalize_kernel(float* __restrict__ out, float inv_n)
{
    float acc = 0.0f;
    for (int i = threadIdx.x; i < RBLOCKS; i += 1024)
        acc += g_partials[i];

    #pragma unroll
    for (int off = 16; off > 0; off >>= 1)
        acc += __shfl_xor_sync(0xFFFFFFFFu, acc, off);

    __shared__ float warp_sums[32];
    int lane = threadIdx.x & 31;
    int wid  = threadIdx.x >> 5;
    if (lane == 0) warp_sums[wid] = acc;
    __syncthreads();

    if (wid == 0) {
        float v = (lane < 32) ? warp_sums[lane] : 0.0f;
        #pragma unroll
        for (int off = 16; off > 0; off >>= 1)
            v += __shfl_xor_sync(0xFFFFFFFFu, v, off);
        if (lane == 0) out[0] = v * inv_n;
    }
}

extern "C" void kernel_launch(void* const* d_in, const int* in_sizes, int n_in,
                              void* d_out, int out_size)
{
    const float* x = (const float*)d_in[0];
    const int*   y = (const int*)d_in[1];
    const float* w = (const float*)d_in[2];
    float* out = (float*)d_out;

    int n  = in_sizes[0];
    int n4 = n / 4;

    wbce_reduce_kernel<<<RBLOCKS, RTHREADS>>>(
        (const float4*)x, (const int4*)y, w, n4);
    wbce_finalize_kernel<<<1, 1024>>>(out, 1.0f / (float)n);
}

// round 2
// speedup vs baseline: 1.0056x; 1.0056x over previous
#include <cuda_runtime.h>
#include <cuda_bf16.h>

// Weighted BCE mean reduction, single fused kernel.
// loss_i = y_i==1 ? -log(x_i)*w1 : -log(1-x_i)*w0 ; out = mean(loss)
// N = 33554432. HBM-bound: 256 MB read -> ~32 us floor at 8 TB/s.
// Last-block-finalize (threadfence reduction) removes the 2nd-kernel launch.

#define RBLOCKS 1184          // 148 SMs * 8 resident blocks (one full wave)
#define RTHREADS 256

__device__ float g_partials[RBLOCKS];
__device__ unsigned int g_count;   // zero-initialized; reset by last block

__global__ __launch_bounds__(RTHREADS, 8)
void wbce_kernel(const float4* __restrict__ x4,
                 const int4* __restrict__ y4,
                 const float* __restrict__ w,
                 int n4, float inv_n,
                 float* __restrict__ out)
{
    const float w0 = __ldg(&w[0]);
    const float w1 = __ldg(&w[1]);

    float acc = 0.0f;
    const int stride = gridDim.x * blockDim.x;
    int i = blockIdx.x * blockDim.x + threadIdx.x;

    // unroll x2: issue 4 wide loads back-to-back before dependent math (MLP)
    for (; i + stride < n4; i += 2 * stride) {
        float4 xa = x4[i];
        float4 xb = x4[i + stride];
        int4   ya = y4[i];
        int4   yb = y4[i + stride];

        float t0 = (ya.x == 1) ? xa.x : (1.0f - xa.x);
        float t1 = (ya.y == 1) ? xa.y : (1.0f - xa.y);
        float t2 = (ya.z == 1) ? xa.z : (1.0f - xa.z);
        float t3 = (ya.w == 1) ? xa.w : (1.0f - xa.w);
        float t4 = (yb.x == 1) ? xb.x : (1.0f - xb.x);
        float t5 = (yb.y == 1) ? xb.y : (1.0f - xb.y);
        float t6 = (yb.z == 1) ? xb.z : (1.0f - xb.z);
        float t7 = (yb.w == 1) ? xb.w : (1.0f - xb.w);

        float u0 = (ya.x == 1) ? w1 : w0;
        float u1 = (ya.y == 1) ? w1 : w0;
        float u2 = (ya.z == 1) ? w1 : w0;
        float u3 = (ya.w == 1) ? w1 : w0;
        float u4 = (yb.x == 1) ? w1 : w0;
        float u5 = (yb.y == 1) ? w1 : w0;
        float u6 = (yb.z == 1) ? w1 : w0;
        float u7 = (yb.w == 1) ? w1 : w0;

        acc = fmaf(-__logf(t0), u0, acc);
        acc = fmaf(-__logf(t1), u1, acc);
        acc = fmaf(-__logf(t2), u2, acc);
        acc = fmaf(-__logf(t3), u3, acc);
        acc = fmaf(-__logf(t4), u4, acc);
        acc = fmaf(-__logf(t5), u5, acc);
        acc = fmaf(-__logf(t6), u6, acc);
        acc = fmaf(-__logf(t7), u7, acc);
    }
    // tail (at most one strided element per thread)
    for (; i < n4; i += stride) {
        float4 xv = x4[i];
        int4   yv = y4[i];
        float t0 = (yv.x == 1) ? xv.x : (1.0f - xv.x);
        float t1 = (yv.y == 1) ? xv.y : (1.0f - xv.y);
        float t2 = (yv.z == 1) ? xv.z : (1.0f - xv.z);
        float t3 = (yv.w == 1) ? xv.w : (1.0f - xv.w);
        float u0 = (yv.x == 1) ? w1 : w0;
        float u1 = (yv.y == 1) ? w1 : w0;
        float u2 = (yv.z == 1) ? w1 : w0;
        float u3 = (yv.w == 1) ? w1 : w0;
        acc = fmaf(-__logf(t0), u0, acc);
        acc = fmaf(-__logf(t1), u1, acc);
        acc = fmaf(-__logf(t2), u2, acc);
        acc = fmaf(-__logf(t3), u3, acc);
    }

    // intra-block reduce
    #pragma unroll
    for (int off = 16; off > 0; off >>= 1)
        acc += __shfl_xor_sync(0xFFFFFFFFu, acc, off);

    __shared__ float warp_sums[RTHREADS / 32];
    __shared__ bool s_is_last;
    int lane = threadIdx.x & 31;
    int wid  = threadIdx.x >> 5;
    if (lane == 0) warp_sums[wid] = acc;
    __syncthreads();

    if (wid == 0) {
        float v = (lane < RTHREADS / 32) ? warp_sums[lane] : 0.0f;
        #pragma unroll
        for (int off = 16; off > 0; off >>= 1)
            v += __shfl_xor_sync(0xFFFFFFFFu, v, off);
        if (lane == 0) {
            g_partials[blockIdx.x] = v;
            __threadfence();
            unsigned int t = atomicAdd(&g_count, 1u);
            s_is_last = (t == gridDim.x - 1);
        }
    }
    __syncthreads();

    // last block folds all partials -> out
    if (s_is_last) {
        volatile float* parts = g_partials;
        float a = 0.0f;
        for (int j = threadIdx.x; j < RBLOCKS; j += RTHREADS)
            a += parts[j];

        #pragma unroll
        for (int off = 16; off > 0; off >>= 1)
            a += __shfl_xor_sync(0xFFFFFFFFu, a, off);

        if (lane == 0) warp_sums[wid] = a;
        __syncthreads();

        if (wid == 0) {
            float v = (lane < RTHREADS / 32) ? warp_sums[lane] : 0.0f;
            #pragma unroll
            for (int off = 16; off > 0; off >>= 1)
                v += __shfl_xor_sync(0xFFFFFFFFu, v, off);
            if (lane == 0) {
                out[0] = v * inv_n;
                g_count = 0;          // reset for next graph replay
            }
        }
    }
}

extern "C" void kernel_launch(void* const* d_in, const int* in_sizes, int n_in,
                              void* d_out, int out_size)
{
    const float* x = (const float*)d_in[0];
    const int*   y = (const int*)d_in[1];
    const float* w = (const float*)d_in[2];
    float* out = (float*)d_out;

    int n  = in_sizes[0];
    int n4 = n / 4;

    wbce_kernel<<<RBLOCKS, RTHREADS>>>(
        (const float4*)x, (const int4*)y, w, n4, 1.0f / (float)n, out);
}